// round 13
// baseline (speedup 1.0000x reference)
#include <cuda_runtime.h>

// StripePolynomial2d — GB300 sm_103a, round 10
//
// vs R9b (23.9us kernel):
//  1. streaming cache hints: x via ld.global.cs, out via st.global.cs so the
//     83KB coefficient table stays L1-resident (stall source was table LDGs
//     falling to L2 under stream eviction)
//  2. t-rebased polynomial (t = u-1): per-pair setup 4 -> 3 ops; coefficients
//     rebased once in the build kernel
//  3. all 9 table LDG.128 of a (c,g) issued before consumption (MLP=9)

#define NW 129
#define PLANE (512*512)

typedef unsigned long long u64;

__device__ __forceinline__ u64 pk(float a, float b) {
    u64 r;
    asm("mov.b64 %0, {%1, %2};" : "=l"(r) : "f"(a), "f"(b));
    return r;
}
__device__ __forceinline__ u64 ffma2(u64 a, u64 b, u64 c) {
    u64 d;
    asm("fma.rn.f32x2 %0, %1, %2, %3;" : "=l"(d) : "l"(a), "l"(b), "l"(c));
    return d;
}
__device__ __forceinline__ u64 fadd2(u64 a, u64 b) {
    u64 d;
    asm("add.rn.f32x2 %0, %1, %2;" : "=l"(d) : "l"(a), "l"(b));
    return d;
}
__device__ __forceinline__ void upk(u64 v, float& lo, float& hi) {
    asm("mov.b64 {%0, %1}, %2;" : "=f"(lo), "=f"(hi) : "l"(v));
}
__device__ __forceinline__ u64 dup_bits(float v) {
    unsigned int b = __float_as_uint(v);
    return ((u64)b << 32) | (u64)b;
}
__device__ __forceinline__ float ldcs(const float* p) {
    float v;
    asm("ld.global.cs.f32 %0, [%1];" : "=f"(v) : "l"(p));
    return v;
}
__device__ __forceinline__ void stcs(float* p, float v) {
    asm("st.global.cs.f32 [%0], %1;" :: "l"(p), "f"(v));
}

// table per (g,c,seg,o): 6 u64 {A0',A1',A2',G1',G2',pad}, t-rebased, lane-dup
__device__ u64 g_tab[1728 * 6];
// prologue tables: (pad, d0-1, int_bits(seg*3), pad)
__device__ float4 g_pre0[512];    // index w        (stripe group 0)
__device__ float4 g_pre1[1023];   // index w+h (g1) and w-h+511 (g2)

__global__ void build_kernel(const float* __restrict__ Wt)
{
    int e = blockIdx.x * 256 + threadIdx.x;

    if (e < 1728) {
        int o = e % 3;
        int s = (e / 3) & 63;
        int c = (e / 192) % 3;
        int g = e / 576;

        auto coef_at = [&](int seg, float& a0, float& a1, float& a2) {
            int k = 2 * seg;
            float w0, w1, w2;
            if (g == 0) {
                const float* p0 = Wt + ((0 * 3 + o) * 3 + c) * NW + k;
                const float* p1 = Wt + ((1 * 3 + o) * 3 + c) * NW + k;
                w0 = p0[0] + p1[0];
                w1 = p0[1] + p1[1];
                w2 = p0[2] + p1[2];
            } else {
                const float* p = Wt + (((g + 1) * 3 + o) * 3 + c) * NW + k;
                w0 = p[0]; w1 = p[1]; w2 = p[2];
            }
            a0 = 0.25f * w1;
            a1 = 0.25f * (0.5f * (w2 - w0));
            a2 = 0.25f * (0.5f * (w0 + w2) - w1);
        };

        float a0, a1, a2;
        coef_at(s, a0, a1, a2);

        float g1 = 0.0f, g2 = 0.0f;
        if (s < 63) {
            float b0, b1, b2;
            coef_at(s + 1, b0, b1, b2);
            // B(u) = P_{s+1}(u-2) - P_s(u), B(1)=0 (continuity)
            float c1p = (b1 - 4.0f * b2) - a1;
            float c2p = b2 - a2;
            g2 = 0.5f * c2p;              // pre-halved: r' = 2*relu
            g1 = 0.5f * (c1p + c2p);
        }

        // rebase to t = u-1:  A'(t)=A(t+1), hh'(t)=hh(t+1)
        float A0p = a0 + a1 + a2;
        float A1p = a1 + 2.0f * a2;
        float A2p = a2;
        float G1p = g1 + g2;
        float G2p = g2;

        u64* dst = g_tab + e * 6;
        dst[0] = dup_bits(A0p);
        dst[1] = dup_bits(A1p);
        dst[2] = dup_bits(A2p);
        dst[3] = dup_bits(G1p);
        dst[4] = dup_bits(G2p);
        dst[5] = 0ULL;
        return;
    }

    // prologue tables (fp64 once, mirrors reference float64 grid math)
    const double RATIO = 512.0 / 513.0;
    float bb;
    float4* dst;
    if (e < 1728 + 512) {
        int i = e - 1728;
        bb = (float)(((double)i * RATIO / 511.0 - 0.5) * 512.0) * 0.125f + 32.0f;
        dst = &g_pre0[i];
    } else if (e < 1728 + 512 + 1023) {
        int i = e - (1728 + 512);
        bb = (float)(((double)i * RATIO / 1022.0 - 0.5) * 512.0) * 0.125f + 32.0f;
        dst = &g_pre1[i];
    } else {
        return;
    }
    float s0f = fminf(fmaxf(floorf(bb), 0.0f), 63.0f);
    float fb  = bb - s0f;                 // exact
    float dm1 = 2.0f * fb - 2.0f;         // d0 - 1  (t = 0.25x + dm1)
    int   s3  = (int)s0f * 3;
    *dst = make_float4(0.0f, dm1, __int_as_float(s3), 0.0f);
}

__global__ __launch_bounds__(256, 3)
void stripe_poly_kernel(const float* __restrict__ x,
                        float* __restrict__ out)
{
    int pid = blockIdx.x * 256 + threadIdx.x;
    int w = pid >> 9;
    int h = pid & 511;

    // table-driven prologue
    float4 P0 = g_pre0[w];
    float4 P1 = g_pre1[w + h];
    float4 P2 = g_pre1[w - h + 511];

    u64 dm2g[3];
    int idxg[3];
    dm2g[0] = pk(P0.y, P0.y); idxg[0] =        __float_as_int(P0.z);
    dm2g[1] = pk(P1.y, P1.y); idxg[1] = 576  + __float_as_int(P1.z);
    dm2g[2] = pk(P2.y, P2.y); idxg[2] = 1152 + __float_as_int(P2.z);

    const u64 Q2   = pk(0.25f, 0.25f);
    const u64 ABSM = 0x7fffffff7fffffffULL;

    u64 acc2[4][3];
    #pragma unroll
    for (int p = 0; p < 4; p++)
        #pragma unroll
        for (int o = 0; o < 3; o++)
            acc2[p][o] = 0ULL;

    #pragma unroll
    for (int c = 0; c < 3; c++) {
        float xv[8];
        #pragma unroll
        for (int b = 0; b < 8; b++)
            xv[b] = ldcs(x + (b * 3 + c) * PLANE + pid);
        u64 xv2[4];
        #pragma unroll
        for (int p = 0; p < 4; p++)
            xv2[p] = pk(xv[2 * p], xv[2 * p + 1]);

        #pragma unroll
        for (int g = 0; g < 3; g++) {
            const u64* tb = g_tab + (u64)(idxg[g] + c * 192) * 6;

            // issue all 9 table loads up front (MLP), then compute
            ulonglong2 v0[3], v1[3], v2[3];
            #pragma unroll
            for (int o = 0; o < 3; o++) {
                const ulonglong2* tp = (const ulonglong2*)(tb + o * 6);
                v0[o] = __ldg(tp);       // A0', A1'
                v1[o] = __ldg(tp + 1);   // A2', G1'
                v2[o] = __ldg(tp + 2);   // G2', pad
            }

            // t = 0.25x + (d0-1) ; r' = t + |t| = 2*relu(t)
            u64 t2[4], r2[4];
            u64 dm2 = dm2g[g];
            #pragma unroll
            for (int p = 0; p < 4; p++) {
                t2[p] = ffma2(Q2, xv2[p], dm2);
                r2[p] = fadd2(t2[p], t2[p] & ABSM);
            }

            #pragma unroll
            for (int o = 0; o < 3; o++) {
                u64 A0 = v0[o].x, A1 = v0[o].y, A2 = v1[o].x;
                u64 G1 = v1[o].y, G2 = v2[o].x;
                #pragma unroll
                for (int p = 0; p < 4; p++) {
                    u64 hh = ffma2(G2, t2[p], G1);
                    u64 s  = ffma2(A2, t2[p], A1);
                    s      = ffma2(s, t2[p], A0);
                    acc2[p][o] = fadd2(acc2[p][o], s);
                    acc2[p][o] = ffma2(r2[p], hh, acc2[p][o]);
                }
            }
        }
    }

    #pragma unroll
    for (int p = 0; p < 4; p++)
        #pragma unroll
        for (int o = 0; o < 3; o++) {
            float lo, hi;
            upk(acc2[p][o], lo, hi);
            stcs(out + ((2 * p)     * 3 + o) * PLANE + pid, lo);
            stcs(out + ((2 * p + 1) * 3 + o) * PLANE + pid, hi);
        }
}

extern "C" void kernel_launch(void* const* d_in, const int* in_sizes, int n_in,
                              void* d_out, int out_size)
{
    const float* x  = (const float*)d_in[0];
    const float* Wt = (const float*)d_in[1];
    if (n_in >= 2 && in_sizes[0] == 4644) {
        Wt = (const float*)d_in[0];
        x  = (const float*)d_in[1];
    }
    float* out = (float*)d_out;

    build_kernel<<<13, 256>>>(Wt);     // 1728 table entries + 512 + 1023 prologue
    stripe_poly_kernel<<<(512 * 512) / 256, 256>>>(x, out);
}